// round 3
// baseline (speedup 1.0000x reference)
#include <cuda_runtime.h>
#include <math.h>

// NormalMixtureEM: B x L windows, K=4 components, 5 SEM iterations.
// One block per row. 256 threads x 4 elements/thread. Window row and
// per-position weights live in registers for all iterations.
// (R2: identical to R1 — prior failures were container-acquisition errors.)

#define LW       1024
#define KC       4
#define N_ITERS  5
#define NTHREADS 256
#define EPT      4          // elements per thread (LW / NTHREADS)
#define EPSF     1e-8f
#define LOG2E_F  1.4426950408889634f
#define SQRT_HALF_LOG2E 0.8493218002880191f   // sqrt(0.5 * log2(e))

__device__ __forceinline__ float ex2f(float x) {
    float r;
    asm("ex2.approx.f32 %0, %1;" : "=f"(r) : "f"(x));
    return r;
}

__global__ void __launch_bounds__(NTHREADS)
em_kernel(const float* __restrict__ windows,
          const float* __restrict__ noise,
          const float* __restrict__ centers,
          const float* __restrict__ scales,
          const float* __restrict__ weights,
          const float* __restrict__ prior_p_param,
          const float* __restrict__ mixw,
          const float* __restrict__ blendp,
          float* __restrict__ out_g,   // [B, L, K]
          float* __restrict__ out_p,   // [B, K]
          float* __restrict__ out_a,   // [B, K]
          float* __restrict__ out_b)   // [B, K]
{
    __shared__ float s_part[8][12];   // per-warp partials: Sg[4], Sx[4], Sxx[4]
    __shared__ float s_stat[16];      // init: per-warp sum / sumsq
    __shared__ float s_a[KC], s_q[KC], s_lw[KC];

    const int row  = blockIdx.x;
    const int tid  = threadIdx.x;
    const int lane = tid & 31;
    const int warp = tid >> 5;
    const float* __restrict__ xr = windows + (size_t)row * LW;

    // ---- load row + per-position weights into registers; row stats ----
    float x[EPT], xx[EPT], wv[EPT];
    float s1 = 0.f, s2 = 0.f;
#pragma unroll
    for (int j = 0; j < EPT; j++) {
        int l = tid + j * NTHREADS;
        float v = xr[l];
        x[j]  = v;
        xx[j] = v * v;
        wv[j] = __expf(mixw[l]);
        s1 += v;
        s2 += v * v;
    }
#pragma unroll
    for (int o = 16; o; o >>= 1) {
        s1 += __shfl_down_sync(0xffffffffu, s1, o);
        s2 += __shfl_down_sync(0xffffffffu, s2, o);
    }
    if (lane == 0) { s_stat[warp] = s1; s_stat[8 + warp] = s2; }
    __syncthreads();

    // ---- per-component persistent state, one component per lane 0..3 ----
    float mean = 0.f, varr = 0.f, prior_p = 0.f, blender = 0.f, omb = 0.f;
    if (tid < KC) {
        float S1 = 0.f, S2 = 0.f;
#pragma unroll
        for (int wn = 0; wn < 8; wn++) { S1 += s_stat[wn]; S2 += s_stat[8 + wn]; }
        mean = S1 * (1.0f / LW);
        varr = (S2 - S1 * S1 * (1.0f / LW)) * (1.0f / (LW - 1));   // ddof=1
        float sd = sqrtf(varr);

        float ak = centers[tid] * sd + mean + noise[row * KC + tid] * sd * 0.01f;
        float bk = fabsf(scales[tid]) * sd;
        float pk = weights[tid];
        prior_p = 1.0f / (1.0f + __expf(-prior_p_param[0]));
        blender = 1.0f / (1.0f + __expf(-blendp[0]));
        omb = 1.0f - blender;

        float binv = __fdividef(1.0f, bk + EPSF);
        s_a[tid]  = ak;
        s_q[tid]  = SQRT_HALF_LOG2E * binv;
        s_lw[tid] = __logf((pk + EPSF) * binv) * LOG2E_F;
    }
    __syncthreads();

    float4* __restrict__ g4out = (float4*)out_g;

    for (int it = 0; it < N_ITERS; it++) {
        const float a0 = s_a[0], a1 = s_a[1], a2 = s_a[2], a3 = s_a[3];
        const float q0 = s_q[0], q1 = s_q[1], q2 = s_q[2], q3 = s_q[3];
        const float w0 = s_lw[0], w1 = s_lw[1], w2 = s_lw[2], w3 = s_lw[3];
        const bool last = (it == N_ITERS - 1);

        float Sg0 = 0.f, Sg1 = 0.f, Sg2 = 0.f, Sg3 = 0.f;
        float Sx0 = 0.f, Sx1 = 0.f, Sx2 = 0.f, Sx3 = 0.f;
        float Sq0 = 0.f, Sq1 = 0.f, Sq2 = 0.f, Sq3 = 0.f;

#pragma unroll
        for (int j = 0; j < EPT; j++) {
            const float xv = x[j];
            float d0 = (xv - a0) * q0;  float lm0 = fmaf(-d0, d0, w0);
            float d1 = (xv - a1) * q1;  float lm1 = fmaf(-d1, d1, w1);
            float d2 = (xv - a2) * q2;  float lm2 = fmaf(-d2, d2, w2);
            float d3 = (xv - a3) * q3;  float lm3 = fmaf(-d3, d3, w3);
            float m = fmaxf(fmaxf(lm0, lm1), fmaxf(lm2, lm3));
            float e0 = ex2f(lm0 - m);
            float e1 = ex2f(lm1 - m);
            float e2 = ex2f(lm2 - m);
            float e3 = ex2f(lm3 - m);
            float s = (e0 + e1) + (e2 + e3);
            float rinv = __fdividef(1.0f, s);
            if (last) {
                float4 g4 = make_float4(e0 * rinv, e1 * rinv, e2 * rinv, e3 * rinv);
                g4out[(size_t)row * LW + tid + j * NTHREADS] = g4;
            }
            float rw = rinv * wv[j];
            float g0 = e0 * rw, g1 = e1 * rw, g2 = e2 * rw, g3 = e3 * rw;
            Sg0 += g0; Sx0 = fmaf(g0, xv, Sx0); Sq0 = fmaf(g0, xx[j], Sq0);
            Sg1 += g1; Sx1 = fmaf(g1, xv, Sx1); Sq1 = fmaf(g1, xx[j], Sq1);
            Sg2 += g2; Sx2 = fmaf(g2, xv, Sx2); Sq2 = fmaf(g2, xx[j], Sq2);
            Sg3 += g3; Sx3 = fmaf(g3, xv, Sx3); Sq3 = fmaf(g3, xx[j], Sq3);
        }

        // warp reduce the 12 accumulators
#pragma unroll
        for (int o = 16; o; o >>= 1) {
            Sg0 += __shfl_down_sync(0xffffffffu, Sg0, o);
            Sg1 += __shfl_down_sync(0xffffffffu, Sg1, o);
            Sg2 += __shfl_down_sync(0xffffffffu, Sg2, o);
            Sg3 += __shfl_down_sync(0xffffffffu, Sg3, o);
            Sx0 += __shfl_down_sync(0xffffffffu, Sx0, o);
            Sx1 += __shfl_down_sync(0xffffffffu, Sx1, o);
            Sx2 += __shfl_down_sync(0xffffffffu, Sx2, o);
            Sx3 += __shfl_down_sync(0xffffffffu, Sx3, o);
            Sq0 += __shfl_down_sync(0xffffffffu, Sq0, o);
            Sq1 += __shfl_down_sync(0xffffffffu, Sq1, o);
            Sq2 += __shfl_down_sync(0xffffffffu, Sq2, o);
            Sq3 += __shfl_down_sync(0xffffffffu, Sq3, o);
        }
        if (lane == 0) {
            s_part[warp][0] = Sg0; s_part[warp][1] = Sg1;
            s_part[warp][2] = Sg2; s_part[warp][3] = Sg3;
            s_part[warp][4] = Sx0; s_part[warp][5] = Sx1;
            s_part[warp][6] = Sx2; s_part[warp][7] = Sx3;
            s_part[warp][8] = Sq0; s_part[warp][9] = Sq1;
            s_part[warp][10] = Sq2; s_part[warp][11] = Sq3;
        }
        __syncthreads();

        // m-step: lane k handles component k
        if (tid < KC) {
            float rg = 0.f, rx = 0.f, rq = 0.f;
#pragma unroll
            for (int wn = 0; wn < 8; wn++) {
                rg += s_part[wn][tid];
                rx += s_part[wn][4 + tid];
                rq += s_part[wn][8 + tid];
            }
            float sg = fmaxf(rg, EPSF);
            float pt = sg + prior_p;
            float t2 = pt + __shfl_xor_sync(0x0000000fu, pt, 1);
            float psum = t2 + __shfl_xor_sync(0x0000000fu, t2, 2);
            float pk = pt / psum;
            float da = rx / sg;
            float ak = da * blender + mean * omb;                 // prior_a = mean
            float dv = (rq - 2.0f * ak * rx + ak * ak * rg) / sg; // sum gw (x-a)^2 / sg
            float bk = sqrtf(dv * blender + varr * omb + EPSF);

            float binv = __fdividef(1.0f, bk + EPSF);
            s_a[tid]  = ak;
            s_q[tid]  = SQRT_HALF_LOG2E * binv;
            s_lw[tid] = __logf((pk + EPSF) * binv) * LOG2E_F;

            if (last) {
                out_p[row * KC + tid] = pk;
                out_a[row * KC + tid] = ak;
                out_b[row * KC + tid] = bk;
            }
        }
        __syncthreads();
    }
}

extern "C" void kernel_launch(void* const* d_in, const int* in_sizes, int n_in,
                              void* d_out, int out_size)
{
    const float* windows  = (const float*)d_in[0];  // [B, L]
    const float* noise    = (const float*)d_in[1];  // [B, K]
    const float* centers  = (const float*)d_in[2];  // [K]
    const float* scales   = (const float*)d_in[3];  // [K]
    const float* weights  = (const float*)d_in[4];  // [K]
    const float* prior_pp = (const float*)d_in[5];  // [1]
    const float* mixw     = (const float*)d_in[6];  // [1, L]
    const float* blend    = (const float*)d_in[7];  // [1]

    const int Brows = in_sizes[0] / LW;

    float* out = (float*)d_out;
    // outputs concatenated in return order: g [B,L,K], p [B,K], a [B,K], b [B,K]
    float* out_g = out;
    float* out_p = out + (size_t)Brows * LW * KC;
    float* out_a = out_p + (size_t)Brows * KC;
    float* out_b = out_a + (size_t)Brows * KC;

    em_kernel<<<Brows, NTHREADS>>>(windows, noise, centers, scales, weights,
                                   prior_pp, mixw, blend,
                                   out_g, out_p, out_a, out_b);
}

// round 5
// speedup vs baseline: 1.2057x; 1.2057x over previous
#include <cuda_runtime.h>
#include <math.h>

// NormalMixtureEM: B x L windows, K=4 components, 5 SEM iterations.
// R4 == R3 resubmit (R4 bench was a container-acquisition failure, no signal):
// 128 threads/row, EPT=8, 9 accumulators (comp3 via row-constant totals),
// Horner 2-FMA log-mixture, fully unrolled iteration loop, float4 loads.

#define LW       1024
#define KC       4
#define NTHREADS 128
#define EPT      8          // elements per thread (LW / NTHREADS)
#define NWARPS   4
#define EPSF     1e-8f
#define HALF_LOG2E 0.7213475204444817f   // 0.5 * log2(e)

__device__ __forceinline__ float ex2f(float x) {
    float r; asm("ex2.approx.f32 %0, %1;" : "=f"(r) : "f"(x)); return r;
}
__device__ __forceinline__ float rcpf(float x) {
    float r; asm("rcp.approx.f32 %0, %1;" : "=f"(r) : "f"(x)); return r;
}

__global__ void __launch_bounds__(NTHREADS)
em_kernel(const float* __restrict__ windows,
          const float* __restrict__ noise,
          const float* __restrict__ centers,
          const float* __restrict__ scales,
          const float* __restrict__ weights,
          const float* __restrict__ prior_p_param,
          const float* __restrict__ mixw,
          const float* __restrict__ blendp,
          float* __restrict__ out_g,   // [B, L, K]
          float* __restrict__ out_p,   // [B, K]
          float* __restrict__ out_a,   // [B, K]
          float* __restrict__ out_b)   // [B, K]
{
    __shared__ float s_part[NWARPS][9];   // per-warp partials: Sg[3], Sx[3], Sq[3]
    __shared__ float s_stat[NWARPS][5];   // init: s1, s2, W, Wx, Wxx per warp
    __shared__ float s_c0[KC], s_c1[KC], s_c2[KC];

    const int row  = blockIdx.x;
    const int tid  = threadIdx.x;
    const int lane = tid & 31;
    const int warp = tid >> 5;

    const float4* __restrict__ xr4 = (const float4*)(windows + (size_t)row * LW);
    const float4* __restrict__ mw4 = (const float4*)mixw;

    // ---- load row (8 consecutive elems/thread) + weights; row stats ----
    float x[EPT], wv[EPT];
    {
        float4 f0 = xr4[2 * tid], f1 = xr4[2 * tid + 1];
        x[0]=f0.x; x[1]=f0.y; x[2]=f0.z; x[3]=f0.w;
        x[4]=f1.x; x[5]=f1.y; x[6]=f1.z; x[7]=f1.w;
        float4 m0 = mw4[2 * tid], m1 = mw4[2 * tid + 1];
        wv[0]=__expf(m0.x); wv[1]=__expf(m0.y); wv[2]=__expf(m0.z); wv[3]=__expf(m0.w);
        wv[4]=__expf(m1.x); wv[5]=__expf(m1.y); wv[6]=__expf(m1.z); wv[7]=__expf(m1.w);
    }
    float s1 = 0.f, s2 = 0.f, W = 0.f, Wx = 0.f, Wxx = 0.f;
#pragma unroll
    for (int j = 0; j < EPT; j++) {
        float v = x[j], wj = wv[j];
        s1 += v; s2 = fmaf(v, v, s2);
        float gx = wj * v;
        W += wj; Wx += gx; Wxx = fmaf(gx, v, Wxx);
    }
#pragma unroll
    for (int o = 16; o; o >>= 1) {
        s1  += __shfl_down_sync(0xffffffffu, s1, o);
        s2  += __shfl_down_sync(0xffffffffu, s2, o);
        W   += __shfl_down_sync(0xffffffffu, W, o);
        Wx  += __shfl_down_sync(0xffffffffu, Wx, o);
        Wxx += __shfl_down_sync(0xffffffffu, Wxx, o);
    }
    if (lane == 0) {
        s_stat[warp][0]=s1; s_stat[warp][1]=s2; s_stat[warp][2]=W;
        s_stat[warp][3]=Wx; s_stat[warp][4]=Wxx;
    }
    __syncthreads();

    // ---- per-component state; lane k (k=0..3 of warp 0) owns component k ----
    float mean=0.f, varr=0.f, prior_p=0.f, blender=0.f, omb=0.f;
    float Wt=0.f, Wxt=0.f, Wxxt=0.f;
    if (tid < KC) {
        float S1=0.f, S2=0.f;
        Wt=0.f; Wxt=0.f; Wxxt=0.f;
#pragma unroll
        for (int wn = 0; wn < NWARPS; wn++) {
            S1 += s_stat[wn][0]; S2 += s_stat[wn][1]; Wt += s_stat[wn][2];
            Wxt += s_stat[wn][3]; Wxxt += s_stat[wn][4];
        }
        mean = S1 * (1.0f / LW);
        varr = (S2 - S1 * S1 * (1.0f / LW)) * (1.0f / (LW - 1));   // ddof=1
        float sd = sqrtf(varr);

        float ak = centers[tid] * sd + mean + noise[row * KC + tid] * sd * 0.01f;
        float bk = fabsf(scales[tid]) * sd;
        float pk = weights[tid];
        prior_p = 1.0f / (1.0f + __expf(-prior_p_param[0]));
        blender = 1.0f / (1.0f + __expf(-blendp[0]));
        omb = 1.0f - blender;

        float binv = rcpf(bk + EPSF);
        float h = HALF_LOG2E * binv * binv;
        s_c2[tid] = -h;
        s_c1[tid] = 2.0f * h * ak;
        s_c0[tid] = __log2f((pk + EPSF) * binv) - h * ak * ak;
    }
    __syncthreads();

    float4* __restrict__ g4out = (float4*)out_g + (size_t)row * LW + 8 * tid;

#pragma unroll
    for (int it = 0; it < 5; it++) {
        const bool last = (it == 4);
        const float c00=s_c0[0], c01=s_c0[1], c02=s_c0[2], c03=s_c0[3];
        const float c10=s_c1[0], c11=s_c1[1], c12=s_c1[2], c13=s_c1[3];
        const float c20=s_c2[0], c21=s_c2[1], c22=s_c2[2], c23=s_c2[3];

        float Sg0=0.f,Sg1=0.f,Sg2=0.f, Sx0=0.f,Sx1=0.f,Sx2=0.f, Sq0=0.f,Sq1=0.f,Sq2=0.f;

#pragma unroll
        for (int j = 0; j < EPT; j++) {
            const float xv = x[j];
            float lm0 = fmaf(fmaf(c20, xv, c10), xv, c00);
            float lm1 = fmaf(fmaf(c21, xv, c11), xv, c01);
            float lm2 = fmaf(fmaf(c22, xv, c12), xv, c02);
            float lm3 = fmaf(fmaf(c23, xv, c13), xv, c03);
            float m = fmaxf(fmaxf(lm0, lm1), fmaxf(lm2, lm3));
            float e0 = ex2f(lm0 - m);
            float e1 = ex2f(lm1 - m);
            float e2 = ex2f(lm2 - m);
            float e3 = ex2f(lm3 - m);
            float rinv = rcpf((e0 + e1) + (e2 + e3));
            if (last) {
                g4out[j] = make_float4(e0 * rinv, e1 * rinv, e2 * rinv, e3 * rinv);
            }
            float rw = rinv * wv[j];
            float xx = xv * xv;
            float g0 = e0 * rw, g1 = e1 * rw, g2 = e2 * rw;
            Sg0 += g0; Sx0 = fmaf(g0, xv, Sx0); Sq0 = fmaf(g0, xx, Sq0);
            Sg1 += g1; Sx1 = fmaf(g1, xv, Sx1); Sq1 = fmaf(g1, xx, Sq1);
            Sg2 += g2; Sx2 = fmaf(g2, xv, Sx2); Sq2 = fmaf(g2, xx, Sq2);
        }

        // warp reduce 9 accumulators
#pragma unroll
        for (int o = 16; o; o >>= 1) {
            Sg0 += __shfl_down_sync(0xffffffffu, Sg0, o);
            Sg1 += __shfl_down_sync(0xffffffffu, Sg1, o);
            Sg2 += __shfl_down_sync(0xffffffffu, Sg2, o);
            Sx0 += __shfl_down_sync(0xffffffffu, Sx0, o);
            Sx1 += __shfl_down_sync(0xffffffffu, Sx1, o);
            Sx2 += __shfl_down_sync(0xffffffffu, Sx2, o);
            Sq0 += __shfl_down_sync(0xffffffffu, Sq0, o);
            Sq1 += __shfl_down_sync(0xffffffffu, Sq1, o);
            Sq2 += __shfl_down_sync(0xffffffffu, Sq2, o);
        }
        if (lane == 0) {
            s_part[warp][0]=Sg0; s_part[warp][1]=Sg1; s_part[warp][2]=Sg2;
            s_part[warp][3]=Sx0; s_part[warp][4]=Sx1; s_part[warp][5]=Sx2;
            s_part[warp][6]=Sq0; s_part[warp][7]=Sq1; s_part[warp][8]=Sq2;
        }
        __syncthreads();

        // m-step: lane k handles component k; comp3 sums from row totals
        if (tid < KC) {
            float rg = 0.f, rx = 0.f, rq = 0.f;
            if (tid < 3) {
#pragma unroll
                for (int wn = 0; wn < NWARPS; wn++) {
                    rg += s_part[wn][tid];
                    rx += s_part[wn][3 + tid];
                    rq += s_part[wn][6 + tid];
                }
            }
            // totals over lanes 0-3 (lane 3 contributes 0)
            float tg = rg + __shfl_xor_sync(0x0000000fu, rg, 1);
            tg += __shfl_xor_sync(0x0000000fu, tg, 2);
            float tx = rx + __shfl_xor_sync(0x0000000fu, rx, 1);
            tx += __shfl_xor_sync(0x0000000fu, tx, 2);
            float tq = rq + __shfl_xor_sync(0x0000000fu, rq, 1);
            tq += __shfl_xor_sync(0x0000000fu, tq, 2);
            if (tid == 3) { rg = Wt - tg; rx = Wxt - tx; rq = Wxxt - tq; }

            float sg = fmaxf(rg, EPSF);
            float pt = sg + prior_p;
            float t2 = pt + __shfl_xor_sync(0x0000000fu, pt, 1);
            float psum = t2 + __shfl_xor_sync(0x0000000fu, t2, 2);
            float pk = pt * rcpf(psum);
            float sginv = rcpf(sg);
            float da = rx * sginv;
            float ak = da * blender + mean * omb;                    // prior_a = mean
            float dv = fmaf(ak, fmaf(ak, rg, -2.0f * rx), rq) * sginv; // Sq-2a Sx+a^2 Sg
            float bk = sqrtf(dv * blender + varr * omb + EPSF);

            float binv = rcpf(bk + EPSF);
            float h = HALF_LOG2E * binv * binv;
            s_c2[tid] = -h;
            s_c1[tid] = 2.0f * h * ak;
            s_c0[tid] = __log2f((pk + EPSF) * binv) - h * ak * ak;

            if (last) {
                out_p[row * KC + tid] = pk;
                out_a[row * KC + tid] = ak;
                out_b[row * KC + tid] = bk;
            }
        }
        __syncthreads();
    }
}

extern "C" void kernel_launch(void* const* d_in, const int* in_sizes, int n_in,
                              void* d_out, int out_size)
{
    const float* windows  = (const float*)d_in[0];  // [B, L]
    const float* noise    = (const float*)d_in[1];  // [B, K]
    const float* centers  = (const float*)d_in[2];  // [K]
    const float* scales   = (const float*)d_in[3];  // [K]
    const float* weights  = (const float*)d_in[4];  // [K]
    const float* prior_pp = (const float*)d_in[5];  // [1]
    const float* mixw     = (const float*)d_in[6];  // [1, L]
    const float* blend    = (const float*)d_in[7];  // [1]

    const int Brows = in_sizes[0] / LW;

    float* out = (float*)d_out;
    float* out_g = out;                                 // [B,L,K]
    float* out_p = out + (size_t)Brows * LW * KC;       // [B,K]
    float* out_a = out_p + (size_t)Brows * KC;
    float* out_b = out_a + (size_t)Brows * KC;

    em_kernel<<<Brows, NTHREADS>>>(windows, noise, centers, scales, weights,
                                   prior_pp, mixw, blend,
                                   out_g, out_p, out_a, out_b);
}

// round 7
// speedup vs baseline: 1.4461x; 1.1994x over previous
#include <cuda_runtime.h>
#include <math.h>

// NormalMixtureEM: B x L windows, K=4 components, 5 SEM iterations.
// R7: 64 threads/row, EPT=16, strided element map (coalesced g stores),
// delta-log-mixture softmax (3 ex2/elem, clamped), exp(mixw) in smem,
// shfl-tree reductions (redux.f32 not assemblable at compute_100).

#define LW       1024
#define KC       4
#define NTHREADS 64
#define EPT      16         // elements per thread (LW / NTHREADS)
#define NWARPS   2
#define EPSF     1e-8f
#define HALF_LOG2E 0.7213475204444817f   // 0.5 * log2(e)

__device__ __forceinline__ float ex2f(float x) {
    float r; asm("ex2.approx.f32 %0, %1;" : "=f"(r) : "f"(x)); return r;
}
__device__ __forceinline__ float rcpf(float x) {
    float r; asm("rcp.approx.f32 %0, %1;" : "=f"(r) : "f"(x)); return r;
}

__global__ void __launch_bounds__(NTHREADS)
em_kernel(const float* __restrict__ windows,
          const float* __restrict__ noise,
          const float* __restrict__ centers,
          const float* __restrict__ scales,
          const float* __restrict__ weights,
          const float* __restrict__ prior_p_param,
          const float* __restrict__ mixw,
          const float* __restrict__ blendp,
          float* __restrict__ out_g,   // [B, L, K]
          float* __restrict__ out_p,   // [B, K]
          float* __restrict__ out_a,   // [B, K]
          float* __restrict__ out_b)   // [B, K]
{
    __shared__ float s_wv[LW];            // exp(mixw), row-independent
    __shared__ float s_part[NWARPS][9];   // per-warp partials: Sg[3], Sx[3], Sq[3]
    __shared__ float s_stat[NWARPS][5];   // init: s1, s2, W, Wx, Wxx per warp
    __shared__ float s_dc0[3], s_dc1[3], s_dc2[3];  // coef diffs for k=1..3

    const int row  = blockIdx.x;
    const int tid  = threadIdx.x;
    const int lane = tid & 31;
    const int warp = tid >> 5;
    const float* __restrict__ xr = windows + (size_t)row * LW;

    // ---- load row (strided: l = tid + j*64), exp-weights to smem; stats ----
    float x[EPT];
    float s1 = 0.f, s2 = 0.f, W = 0.f, Wx = 0.f, Wxx = 0.f;
#pragma unroll
    for (int j = 0; j < EPT; j++) {
        const int l = tid + j * NTHREADS;
        float v = xr[l];
        x[j] = v;
        float wj = __expf(mixw[l]);
        s_wv[l] = wj;
        s1 += v; s2 = fmaf(v, v, s2);
        float gx = wj * v;
        W += wj; Wx += gx; Wxx = fmaf(gx, v, Wxx);
    }
#pragma unroll
    for (int o = 16; o; o >>= 1) {
        s1  += __shfl_down_sync(0xffffffffu, s1, o);
        s2  += __shfl_down_sync(0xffffffffu, s2, o);
        W   += __shfl_down_sync(0xffffffffu, W, o);
        Wx  += __shfl_down_sync(0xffffffffu, Wx, o);
        Wxx += __shfl_down_sync(0xffffffffu, Wxx, o);
    }
    if (lane == 0) {
        s_stat[warp][0]=s1; s_stat[warp][1]=s2; s_stat[warp][2]=W;
        s_stat[warp][3]=Wx; s_stat[warp][4]=Wxx;
    }
    __syncthreads();

    // ---- per-component state; lane k (k=0..3 of warp 0) owns component k ----
    float mean=0.f, varr=0.f, prior_p=0.f, blender=0.f, omb=0.f;
    float Wt=0.f, Wxt=0.f, Wxxt=0.f;
    if (tid < KC) {
        float S1=0.f, S2=0.f;
#pragma unroll
        for (int wn = 0; wn < NWARPS; wn++) {
            S1 += s_stat[wn][0]; S2 += s_stat[wn][1]; Wt += s_stat[wn][2];
            Wxt += s_stat[wn][3]; Wxxt += s_stat[wn][4];
        }
        mean = S1 * (1.0f / LW);
        varr = (S2 - S1 * S1 * (1.0f / LW)) * (1.0f / (LW - 1));   // ddof=1
        float sd = sqrtf(varr);

        float ak = centers[tid] * sd + mean + noise[row * KC + tid] * sd * 0.01f;
        float bk = fabsf(scales[tid]) * sd;
        float pk = weights[tid];
        prior_p = 1.0f / (1.0f + __expf(-prior_p_param[0]));
        blender = 1.0f / (1.0f + __expf(-blendp[0]));
        omb = 1.0f - blender;

        float binv = rcpf(bk + EPSF);
        float h = HALF_LOG2E * binv * binv;
        float c2 = -h;
        float c1 = 2.0f * h * ak;
        float c0 = __log2f((pk + EPSF) * binv) - h * ak * ak;
        float c00 = __shfl_sync(0x0000000fu, c0, 0);
        float c10 = __shfl_sync(0x0000000fu, c1, 0);
        float c20 = __shfl_sync(0x0000000fu, c2, 0);
        if (tid >= 1) {
            s_dc0[tid - 1] = c0 - c00;
            s_dc1[tid - 1] = c1 - c10;
            s_dc2[tid - 1] = c2 - c20;
        }
    }
    __syncthreads();

    float4* __restrict__ g4row = (float4*)out_g + (size_t)row * LW;

#pragma unroll
    for (int it = 0; it < 5; it++) {
        const bool last = (it == 4);
        const float d01=s_dc0[0], d02=s_dc0[1], d03=s_dc0[2];
        const float d11=s_dc1[0], d12=s_dc1[1], d13=s_dc1[2];
        const float d21=s_dc2[0], d22=s_dc2[1], d23=s_dc2[2];

        float Sg0=0.f,Sg1=0.f,Sg2=0.f, Sx0=0.f,Sx1=0.f,Sx2=0.f, Sq0=0.f,Sq1=0.f,Sq2=0.f;

#pragma unroll
        for (int j = 0; j < EPT; j++) {
            const float xv = x[j];
            // dlm_k = lm_k - lm_0 as quadratic in x (k = 1..3), clamped
            float e1 = ex2f(fminf(fmaf(fmaf(d21, xv, d11), xv, d01), 80.f));
            float e2 = ex2f(fminf(fmaf(fmaf(d22, xv, d12), xv, d02), 80.f));
            float e3 = ex2f(fminf(fmaf(fmaf(d23, xv, d13), xv, d03), 80.f));
            float rinv = rcpf(1.0f + e1 + (e2 + e3));
            if (last) {
                g4row[tid + j * NTHREADS] =
                    make_float4(rinv, e1 * rinv, e2 * rinv, e3 * rinv);
            }
            float rw = rinv * s_wv[tid + j * NTHREADS];
            float xx = xv * xv;
            float g1 = e1 * rw, g2 = e2 * rw;
            Sg0 += rw; Sx0 = fmaf(rw, xv, Sx0); Sq0 = fmaf(rw, xx, Sq0);
            Sg1 += g1; Sx1 = fmaf(g1, xv, Sx1); Sq1 = fmaf(g1, xx, Sq1);
            Sg2 += g2; Sx2 = fmaf(g2, xv, Sx2); Sq2 = fmaf(g2, xx, Sq2);
        }

        // warp shfl-tree reduce 9 accumulators
#pragma unroll
        for (int o = 16; o; o >>= 1) {
            Sg0 += __shfl_down_sync(0xffffffffu, Sg0, o);
            Sg1 += __shfl_down_sync(0xffffffffu, Sg1, o);
            Sg2 += __shfl_down_sync(0xffffffffu, Sg2, o);
            Sx0 += __shfl_down_sync(0xffffffffu, Sx0, o);
            Sx1 += __shfl_down_sync(0xffffffffu, Sx1, o);
            Sx2 += __shfl_down_sync(0xffffffffu, Sx2, o);
            Sq0 += __shfl_down_sync(0xffffffffu, Sq0, o);
            Sq1 += __shfl_down_sync(0xffffffffu, Sq1, o);
            Sq2 += __shfl_down_sync(0xffffffffu, Sq2, o);
        }
        if (lane == 0) {
            s_part[warp][0]=Sg0; s_part[warp][1]=Sg1; s_part[warp][2]=Sg2;
            s_part[warp][3]=Sx0; s_part[warp][4]=Sx1; s_part[warp][5]=Sx2;
            s_part[warp][6]=Sq0; s_part[warp][7]=Sq1; s_part[warp][8]=Sq2;
        }
        __syncthreads();

        // m-step: lane k handles component k; comp3 sums from row totals
        if (tid < KC) {
            float rg = 0.f, rx = 0.f, rq = 0.f;
            if (tid < 3) {
#pragma unroll
                for (int wn = 0; wn < NWARPS; wn++) {
                    rg += s_part[wn][tid];
                    rx += s_part[wn][3 + tid];
                    rq += s_part[wn][6 + tid];
                }
            }
            // totals over lanes 0-3 (lane 3 contributes 0)
            float tg = rg + __shfl_xor_sync(0x0000000fu, rg, 1);
            tg += __shfl_xor_sync(0x0000000fu, tg, 2);
            float tx = rx + __shfl_xor_sync(0x0000000fu, rx, 1);
            tx += __shfl_xor_sync(0x0000000fu, tx, 2);
            float tq = rq + __shfl_xor_sync(0x0000000fu, rq, 1);
            tq += __shfl_xor_sync(0x0000000fu, tq, 2);
            if (tid == 3) { rg = Wt - tg; rx = Wxt - tx; rq = Wxxt - tq; }

            float sg = fmaxf(rg, EPSF);
            float pt = sg + prior_p;
            float t2 = pt + __shfl_xor_sync(0x0000000fu, pt, 1);
            float psum = t2 + __shfl_xor_sync(0x0000000fu, t2, 2);
            float pk = pt * rcpf(psum);
            float sginv = rcpf(sg);
            float da = rx * sginv;
            float ak = da * blender + mean * omb;                      // prior_a = mean
            float dv = fmaf(ak, fmaf(ak, rg, -2.0f * rx), rq) * sginv; // Sq-2aSx+a^2Sg
            float bk = sqrtf(dv * blender + varr * omb + EPSF);

            float binv = rcpf(bk + EPSF);
            float h = HALF_LOG2E * binv * binv;
            float c2 = -h;
            float c1 = 2.0f * h * ak;
            float c0 = __log2f((pk + EPSF) * binv) - h * ak * ak;
            float c00 = __shfl_sync(0x0000000fu, c0, 0);
            float c10 = __shfl_sync(0x0000000fu, c1, 0);
            float c20 = __shfl_sync(0x0000000fu, c2, 0);
            if (tid >= 1) {
                s_dc0[tid - 1] = c0 - c00;
                s_dc1[tid - 1] = c1 - c10;
                s_dc2[tid - 1] = c2 - c20;
            }

            if (last) {
                out_p[row * KC + tid] = pk;
                out_a[row * KC + tid] = ak;
                out_b[row * KC + tid] = bk;
            }
        }
        __syncthreads();
    }
}

extern "C" void kernel_launch(void* const* d_in, const int* in_sizes, int n_in,
                              void* d_out, int out_size)
{
    const float* windows  = (const float*)d_in[0];  // [B, L]
    const float* noise    = (const float*)d_in[1];  // [B, K]
    const float* centers  = (const float*)d_in[2];  // [K]
    const float* scales   = (const float*)d_in[3];  // [K]
    const float* weights  = (const float*)d_in[4];  // [K]
    const float* prior_pp = (const float*)d_in[5];  // [1]
    const float* mixw     = (const float*)d_in[6];  // [1, L]
    const float* blend    = (const float*)d_in[7];  // [1]

    const int Brows = in_sizes[0] / LW;

    float* out = (float*)d_out;
    float* out_g = out;                                 // [B,L,K]
    float* out_p = out + (size_t)Brows * LW * KC;       // [B,K]
    float* out_a = out_p + (size_t)Brows * KC;
    float* out_b = out_a + (size_t)Brows * KC;

    em_kernel<<<Brows, NTHREADS>>>(windows, noise, centers, scales, weights,
                                   prior_pp, mixw, blend,
                                   out_g, out_p, out_a, out_b);
}